// round 7
// baseline (speedup 1.0000x reference)
#include <cuda_runtime.h>
#include <cstdint>

// Z gate (DIM=2, S=1) on wires (0,5,11) of L=24 qubits.
// out[a] = x_real[a] * (-1)^(parity of bits {23,18,12} of a).
// Output dtype float32 (real part), N elements. 64 MB read + 64 MB write.
//
// R7: MLP=4 front-batched float4 loads per thread + streaming cache hints
// (__ldcs/__stcs) — data is touched exactly once, evict-first.

__global__ void __launch_bounds__(256) z_real_vec4x4(
    const float4* __restrict__ xr,
    float4* __restrict__ out,
    int n16)   // number of 16-float groups
{
    int t = blockIdx.x * blockDim.x + threadIdx.x;
    if (t >= n16) return;

    // This thread handles float4s [4t, 4t+3] = amplitudes [16t, 16t+15].
    int base4 = t << 2;

    // Sign: lowest parity bit is 12, so it is constant across any 16
    // consecutive amplitudes (block of 4096 shares a sign).
    unsigned a = (unsigned)base4 << 2;
    unsigned par = ((a >> 23) ^ (a >> 18) ^ (a >> 12)) & 1u;
    float s = par ? -1.0f : 1.0f;

    // Front-batch 4 independent loads (MLP=4).
    float4 r0 = __ldcs(xr + base4 + 0);
    float4 r1 = __ldcs(xr + base4 + 1);
    float4 r2 = __ldcs(xr + base4 + 2);
    float4 r3 = __ldcs(xr + base4 + 3);

    __stcs(out + base4 + 0, make_float4(r0.x * s, r0.y * s, r0.z * s, r0.w * s));
    __stcs(out + base4 + 1, make_float4(r1.x * s, r1.y * s, r1.z * s, r1.w * s));
    __stcs(out + base4 + 2, make_float4(r2.x * s, r2.y * s, r2.z * s, r2.w * s));
    __stcs(out + base4 + 3, make_float4(r3.x * s, r3.y * s, r3.z * s, r3.w * s));
}

// Alignment/tail-safe scalar fallback (not expected for N=2^24).
__global__ void __launch_bounds__(256) z_real_scalar(
    const float* __restrict__ xr,
    float* __restrict__ out,
    int n)
{
    int a = blockIdx.x * blockDim.x + threadIdx.x;
    if (a >= n) return;

    unsigned u = (unsigned)a;
    unsigned par = ((u >> 23) ^ (u >> 18) ^ (u >> 12)) & 1u;
    float s = par ? -1.0f : 1.0f;
    out[a] = xr[a] * s;
}

extern "C" void kernel_launch(void* const* d_in, const int* in_sizes, int n_in,
                              void* d_out, int out_size) {
    const float* xr = (const float*)d_in[0];

    int n = in_sizes[0];
    if (out_size < n) n = out_size;

    bool vec_ok = ((n & 15) == 0) &&
                  (((uintptr_t)xr    & 15u) == 0) &&
                  (((uintptr_t)d_out & 15u) == 0);

    if (vec_ok) {
        int n16 = n >> 4;   // 16 amplitudes (4 float4s) per thread
        z_real_vec4x4<<<(n16 + 255) / 256, 256>>>(
            (const float4*)xr, (float4*)d_out, n16);
    } else {
        z_real_scalar<<<(n + 255) / 256, 256>>>(
            xr, (float*)d_out, n);
    }
}

// round 8
// speedup vs baseline: 1.2168x; 1.2168x over previous
#include <cuda_runtime.h>
#include <cstdint>

// Z gate (DIM=2, S=1) on wires (0,5,11) of L=24 qubits.
// out[a] = x_real[a] * (-1)^(parity of bits {23,18,12} of a).
// Output: N float32 (real part). 64 MB read + 64 MB write.
//
// R8: identical structure to R6 (1 float4/thread, best so far) with ONE
// change: stores use .cs (evict-first) so the 64 MB output stream does not
// evict the 64 MB input from L2. Input is re-read every graph replay and
// should become fully L2-resident -> DRAM traffic ~= writes only.

__global__ void __launch_bounds__(256) z_real_vec4(
    const float4* __restrict__ xr,
    float4* __restrict__ out,
    int n4)
{
    int t = blockIdx.x * blockDim.x + threadIdx.x;
    if (t >= n4) return;

    unsigned a = (unsigned)t << 2;   // first amplitude of this float4
    // lowest parity bit is 12 -> sign constant across 4096 consecutive amps
    unsigned par = ((a >> 23) ^ (a >> 18) ^ (a >> 12)) & 1u;
    float s = par ? -1.0f : 1.0f;

    float4 r = xr[t];                // default .ca: keep input in L2
    __stcs(out + t, make_float4(r.x * s, r.y * s, r.z * s, r.w * s));
}

// Alignment/tail-safe scalar fallback (not expected for N=2^24).
__global__ void __launch_bounds__(256) z_real_scalar(
    const float* __restrict__ xr,
    float* __restrict__ out,
    int n)
{
    int a = blockIdx.x * blockDim.x + threadIdx.x;
    if (a >= n) return;

    unsigned u = (unsigned)a;
    unsigned par = ((u >> 23) ^ (u >> 18) ^ (u >> 12)) & 1u;
    float s = par ? -1.0f : 1.0f;
    out[a] = xr[a] * s;
}

extern "C" void kernel_launch(void* const* d_in, const int* in_sizes, int n_in,
                              void* d_out, int out_size) {
    const float* xr = (const float*)d_in[0];

    int n = in_sizes[0];
    if (out_size < n) n = out_size;

    bool vec_ok = ((n & 3) == 0) &&
                  (((uintptr_t)xr    & 15u) == 0) &&
                  (((uintptr_t)d_out & 15u) == 0);

    if (vec_ok) {
        int n4 = n >> 2;
        z_real_vec4<<<(n4 + 255) / 256, 256>>>(
            (const float4*)xr, (float4*)d_out, n4);
    } else {
        z_real_scalar<<<(n + 255) / 256, 256>>>(
            xr, (float*)d_out, n);
    }
}

// round 10
// speedup vs baseline: 1.3710x; 1.1267x over previous
#include <cuda_runtime.h>
#include <cstdint>

// Z gate (DIM=2, S=1) on wires (0,5,11) of L=24 qubits.
// out[a] = x_real[a] * (-1)^(parity of bits {23,18,12} of a).
// Output: N float32 (real part). 64 MB read (mostly L2-resident across graph
// replays) + 64 MB write (streamed to DRAM with .cs).
//
// R9: coalesced MLP=4. Block tile = 1024 float4s (4096 amplitudes); thread t
// loads {t, t+256, t+512, t+768} -> each LDG.128 is 4 contiguous 128B lines
// (unlike R7's per-thread-chunk layout which hit 16 lines/LDG). 4 independent
// loads in flight per warp hides L2/DRAM latency. Sign is uniform per block
// (tile = exactly one 4096-amplitude sign run).

__global__ void __launch_bounds__(256) z_real_vec4_mlp4(
    const float4* __restrict__ xr,
    float4* __restrict__ out)
{
    int base = blockIdx.x * 1024 + threadIdx.x;

    // amplitude index >> 12 == blockIdx.x for the whole tile
    unsigned b = blockIdx.x;
    unsigned par = (b ^ (b >> 6) ^ (b >> 11)) & 1u;
    float s = par ? -1.0f : 1.0f;

    // 4 independent coalesced loads (MLP=4), default .ca policy.
    float4 r0 = xr[base + 0 * 256];
    float4 r1 = xr[base + 1 * 256];
    float4 r2 = xr[base + 2 * 256];
    float4 r3 = xr[base + 3 * 256];

    __stcs(out + base + 0 * 256, make_float4(r0.x * s, r0.y * s, r0.z * s, r0.w * s));
    __stcs(out + base + 1 * 256, make_float4(r1.x * s, r1.y * s, r1.z * s, r1.w * s));
    __stcs(out + base + 2 * 256, make_float4(r2.x * s, r2.y * s, r2.z * s, r2.w * s));
    __stcs(out + base + 3 * 256, make_float4(r3.x * s, r3.y * s, r3.z * s, r3.w * s));
}

// Generic 1-float4/thread path for sizes not divisible by the tile.
__global__ void __launch_bounds__(256) z_real_vec4(
    const float4* __restrict__ xr,
    float4* __restrict__ out,
    int n4)
{
    int t = blockIdx.x * blockDim.x + threadIdx.x;
    if (t >= n4) return;

    unsigned a = (unsigned)t << 2;
    unsigned par = ((a >> 23) ^ (a >> 18) ^ (a >> 12)) & 1u;
    float s = par ? -1.0f : 1.0f;

    float4 r = xr[t];
    __stcs(out + t, make_float4(r.x * s, r.y * s, r.z * s, r.w * s));
}

// Alignment/tail-safe scalar fallback.
__global__ void __launch_bounds__(256) z_real_scalar(
    const float* __restrict__ xr,
    float* __restrict__ out,
    int n)
{
    int a = blockIdx.x * blockDim.x + threadIdx.x;
    if (a >= n) return;

    unsigned u = (unsigned)a;
    unsigned par = ((u >> 23) ^ (u >> 18) ^ (u >> 12)) & 1u;
    float s = par ? -1.0f : 1.0f;
    out[a] = xr[a] * s;
}

extern "C" void kernel_launch(void* const* d_in, const int* in_sizes, int n_in,
                              void* d_out, int out_size) {
    const float* xr = (const float*)d_in[0];

    int n = in_sizes[0];
    if (out_size < n) n = out_size;

    bool aligned = (((uintptr_t)xr    & 15u) == 0) &&
                   (((uintptr_t)d_out & 15u) == 0);

    if (aligned && (n % 4096) == 0) {
        int n4 = n >> 2;                 // float4 count
        int blocks = n4 / 1024;          // 1024 float4s per block
        z_real_vec4_mlp4<<<blocks, 256>>>((const float4*)xr, (float4*)d_out);
    } else if (aligned && (n & 3) == 0) {
        int n4 = n >> 2;
        z_real_vec4<<<(n4 + 255) / 256, 256>>>(
            (const float4*)xr, (float4*)d_out, n4);
    } else {
        z_real_scalar<<<(n + 255) / 256, 256>>>(
            xr, (float*)d_out, n);
    }
}